// round 15
// baseline (speedup 1.0000x reference)
#include <cuda_runtime.h>
#include <cuda_fp16.h>
#include <cstdint>

#define BB 2
#define TT 2048
#define DD 512
#define HH 8
#define DH 64
#define NINNER 512
#define MAXLAG 5
#define BT (BB*TT)
#define NBH (BB*HH)
#define NQT 16
#define MAXSEG 4
#define LOG2E 1.4426950408889634f

// Scratch (device globals; no allocation allowed)
__device__ __half g_qh[BB*HH*TT*DH];
__device__ __half g_kh[BB*HH*TT*DH];
__device__ __half g_vh[BB*HH*TT*DH];
__device__ __half g_ah[BT*NINNER];
__device__ __half g_xh[BT*DD];
__device__ __half g_wh[4*DD*NINNER];   // W^T (half): WT[n][k] = W[k][n]
__device__ float g_lagp[HH*(MAXLAG+1)];
// split-KV partials
__device__ float g_pO[NBH*NQT*MAXSEG*128*64];
__device__ float g_pl[NBH*NQT*MAXSEG*128];

// work-unit table, LPT order
__device__ const uint8_t c_qt[40] = {
    3,4,5,6,7,7,8,8,9,9,10,10,11,11,11,12,12,12,13,13,13,14,14,14,15,15,15,15,
    2,6,10,14, 1,5,9,13, 0,4,8,12};
__device__ const uint8_t c_sg[40] = {
    0,0,0,0,0,1,0,1,0,1,0,1,0,1,2,0,1,2,0,1,2,0,1,2,0,1,2,3,
    0,1,2,3, 0,1,2,3, 0,1,2,3};

// ---------------------------------------------------------------------------
static __device__ __forceinline__ uint32_t pkh2(float a, float b) {
    __half2 h = __floats2half2_rn(a, b);
    return *(uint32_t*)&h;
}
static __device__ __forceinline__ void mma16(float* d, const uint32_t* a,
                                             uint32_t b0, uint32_t b1) {
    asm volatile(
        "mma.sync.aligned.m16n8k16.row.col.f32.f16.f16.f32 "
        "{%0,%1,%2,%3},{%4,%5,%6,%7},{%8,%9},{%0,%1,%2,%3};"
        : "+f"(d[0]), "+f"(d[1]), "+f"(d[2]), "+f"(d[3])
        : "r"(a[0]), "r"(a[1]), "r"(a[2]), "r"(a[3]), "r"(b0), "r"(b1));
}
#define EX2H2(v) asm("ex2.approx.f16x2 %0, %0;" : "+r"(v))
#define LDSM4(r0,r1,r2,r3, addr) \
    asm volatile("ldmatrix.sync.aligned.m8n8.x4.shared.b16 {%0,%1,%2,%3}, [%4];" \
        : "=r"(r0),"=r"(r1),"=r"(r2),"=r"(r3) : "r"(addr))
#define LDSM4T(r0,r1,r2,r3, addr) \
    asm volatile("ldmatrix.sync.aligned.m8n8.x4.trans.shared.b16 {%0,%1,%2,%3}, [%4];" \
        : "=r"(r0),"=r"(r1),"=r"(r2),"=r"(r3) : "r"(addr))
static __device__ __forceinline__ uint32_t smem_u32(const void* p) {
    uint32_t a;
    asm("{ .reg .u64 t; cvta.to.shared.u64 t, %1; cvt.u32.u64 %0, t; }" : "=r"(a) : "l"(p));
    return a;
}
#define CP_ASYNC16(dst, src) \
    asm volatile("cp.async.cg.shared.global [%0], [%1], 16;" :: "r"(dst), "l"(src))
#define CP_COMMIT() asm volatile("cp.async.commit_group;" ::: "memory")
#define CP_WAIT0()  asm volatile("cp.async.wait_group 0;" ::: "memory")

// ---------------------------------------------------------------------------
// Kernel C: x (fp32) -> g_xh (half). Block 0 also computes lag softmax.
// ---------------------------------------------------------------------------
__global__ __launch_bounds__(256) void cvt_x_kernel(
    const float* __restrict__ x, const float* __restrict__ lw)
{
    int i = blockIdx.x * 256 + threadIdx.x;
    float4 v0 = ((const float4*)x)[2*i];
    float4 v1 = ((const float4*)x)[2*i + 1];
    uint4 o = make_uint4(pkh2(v0.x, v0.y), pkh2(v0.z, v0.w),
                         pkh2(v1.x, v1.y), pkh2(v1.z, v1.w));
    ((uint4*)g_xh)[i] = o;

    if (blockIdx.x == 0 && threadIdx.x < HH) {
        int h = threadIdx.x;
        float vals[MAXLAG+1];
        float m = -1e30f;
        #pragma unroll
        for (int k = 0; k <= MAXLAG; k++) { vals[k] = lw[h*(MAXLAG+1)+k]; m = fmaxf(m, vals[k]); }
        float s = 0.f;
        #pragma unroll
        for (int k = 0; k <= MAXLAG; k++) { vals[k] = __expf(vals[k]-m); s += vals[k]; }
        #pragma unroll
        for (int k = 0; k <= MAXLAG; k++) g_lagp[h*(MAXLAG+1)+k] = vals[k]/s;
    }
}

// ---------------------------------------------------------------------------
// Kernel T: transpose 4 weight matrices -> g_wh (half W^T)
// ---------------------------------------------------------------------------
__global__ __launch_bounds__(256) void transpose_w_kernel(
    const float* __restrict__ Wq, const float* __restrict__ Wk,
    const float* __restrict__ Wv, const float* __restrict__ Wo)
{
    __shared__ float tile[32][33];
    const float* W = (blockIdx.z == 0) ? Wq : (blockIdx.z == 1) ? Wk
                    : (blockIdx.z == 2) ? Wv : Wo;
    __half* WT = g_wh + (size_t)blockIdx.z * DD * NINNER;
    int x0 = blockIdx.x * 32, y0 = blockIdx.y * 32;
    int tx = threadIdx.x & 31, ty = threadIdx.x >> 5;
    #pragma unroll
    for (int i = 0; i < 4; i++)
        tile[ty + i*8][tx] = W[(size_t)(y0 + ty + i*8) * NINNER + x0 + tx];
    __syncthreads();
    #pragma unroll
    for (int i = 0; i < 4; i++)
        WT[(size_t)(x0 + ty + i*8) * DD + y0 + tx] = __float2half(tile[tx][ty + i*8]);
}

// ---------------------------------------------------------------------------
// fp16 GEMM mainloop: 128x128 tile, K=512, 4-stage cp.async ring,
// ONE wait+barrier per TWO k-chunks. Dynamic smem.
// ---------------------------------------------------------------------------
#define GSH 40
#define GST (128 * GSH * 2)         // per-stage bytes per matrix (10240)
#define GSMEM (4 * GST * 2)         // 81920 bytes

static __device__ __forceinline__ void mma_mainloop_h(
    const __half* __restrict__ A, const __half* __restrict__ Bt,
    int row0, int col0, __half* As, __half* Bs, float acc[2][8][4])
{
    int tid = threadIdx.x, lane = tid & 31, wid = tid >> 5;
    int sub = lane >> 3, lr = lane & 7;
    int wm = wid & 3, wn = wid >> 2;
    int m0 = wm * 32, n0 = wn * 64;

    int fr = tid >> 2, fc = tid & 3;
    const char* pa = (const char*)(A  + (size_t)(row0 + fr) * DD + fc * 8);
    const char* pb = (const char*)(Bt + (size_t)(col0 + fr) * DD + fc * 8);
    const long RS = (long)64 * DD * 2;
    const uint32_t HM = 64 * GSH * 2;   // rows 64..127 offset (5120B)

    uint32_t ad0 = smem_u32(&As[fr * GSH + fc * 8]);
    uint32_t bd0 = smem_u32(&Bs[fr * GSH + fc * 8]);
    uint32_t sA0 = smem_u32(As) + ((m0 + (sub&1)*8 + lr) * GSH + (sub>>1)*8) * 2;
    uint32_t sB0 = smem_u32(Bs) + ((n0 + (sub>>1)*8 + lr) * GSH + (sub&1)*8) * 2;

    #pragma unroll
    for (int c0 = 0; c0 < 2; c0++) {
        long off = (long)c0 * 64;
        uint32_t sb = c0 * GST;
        CP_ASYNC16(ad0 + sb, pa + off);       CP_ASYNC16(ad0 + sb + HM, pa + RS + off);
        CP_ASYNC16(bd0 + sb, pb + off);       CP_ASYNC16(bd0 + sb + HM, pb + RS + off);
        CP_COMMIT();
    }

    for (int c = 0; c < 16; c += 2) {
        CP_WAIT0();
        __syncthreads();
        #pragma unroll
        for (int f = 2; f < 4; f++) {
            if (c + f < 16) {
                uint32_t sb = ((c + f) & 3) * GST;
                long off = (long)(c + f) * 64;
                CP_ASYNC16(ad0 + sb, pa + off);       CP_ASYNC16(ad0 + sb + HM, pa + RS + off);
                CP_ASYNC16(bd0 + sb, pb + off);       CP_ASYNC16(bd0 + sb + HM, pb + RS + off);
                CP_COMMIT();
            }
        }
        #pragma unroll
        for (int d = 0; d < 2; d++) {
            uint32_t st = (uint32_t)((c + d) & 3) * GST;
            uint32_t sA = sA0 + st, sB = sB0 + st;
            uint32_t a[2][2][4];
            #pragma unroll
            for (int kk = 0; kk < 2; kk++)
                #pragma unroll
                for (int mf = 0; mf < 2; mf++)
                    LDSM4(a[kk][mf][0], a[kk][mf][1], a[kk][mf][2], a[kk][mf][3],
                          sA + mf * (16 * GSH * 2) + kk * 32);
            uint32_t bB[2][4];
            LDSM4(bB[0][0], bB[0][1], bB[0][2], bB[0][3], sB);
            #pragma unroll
            for (int it = 0; it < 8; it++) {
                int kk = it >> 2, p = it & 3;
                if (it + 1 < 8) {
                    int nkk = (it + 1) >> 2, np = (it + 1) & 3;
                    LDSM4(bB[(it+1)&1][0], bB[(it+1)&1][1], bB[(it+1)&1][2], bB[(it+1)&1][3],
                          sB + np * (16 * GSH * 2) + nkk * 32);
                }
                const uint32_t* b = bB[it & 1];
                mma16(acc[0][2*p],   a[kk][0], b[0], b[1]);
                mma16(acc[0][2*p+1], a[kk][0], b[2], b[3]);
                mma16(acc[1][2*p],   a[kk][1], b[0], b[1]);
                mma16(acc[1][2*p+1], a[kk][1], b[2], b[3]);
            }
        }
    }
}

// ---------------------------------------------------------------------------
// Kernel 1: QKV GEMM. grid (4, 32, 3) x 256. Writes half [b,h,t,d].
// ---------------------------------------------------------------------------
__global__ __launch_bounds__(256, 2) void gemm_qkv_mma() {
    extern __shared__ __half dsm[];
    __half* As = dsm;
    __half* Bs = dsm + 4 * 128 * GSH;
    int z = blockIdx.z;
    const __half* Bt = g_wh + (size_t)z * DD * NINNER;
    __half* out = (z == 0) ? g_qh : (z == 1) ? g_kh : g_vh;
    int row0 = blockIdx.y * 128, col0 = blockIdx.x * 128;

    float acc[2][8][4];
    #pragma unroll
    for (int i = 0; i < 2; i++)
        #pragma unroll
        for (int j = 0; j < 8; j++)
            #pragma unroll
            for (int r = 0; r < 4; r++) acc[i][j][r] = 0.f;

    mma_mainloop_h(g_xh, Bt, row0, col0, As, Bs, acc);

    int tid = threadIdx.x, wid = tid >> 5, lane = tid & 31;
    int g = lane >> 2, tig = lane & 3;
    int wm = wid & 3, wn = wid >> 2;
    int h = (col0 >> 6) + wn;
    #pragma unroll
    for (int mf = 0; mf < 2; mf++) {
        int r0 = row0 + wm * 32 + mf * 16 + g;
        int r1 = r0 + 8;
        int b0_ = r0 >> 11, t0 = r0 & (TT-1);
        int b1_ = r1 >> 11, t1 = r1 & (TT-1);
        __half* p0 = out + ((size_t)(b0_*HH + h)*TT + t0)*DH;
        __half* p1 = out + ((size_t)(b1_*HH + h)*TT + t1)*DH;
        #pragma unroll
        for (int nf = 0; nf < 8; nf++) {
            int d = nf * 8 + 2 * tig;
            *(uint32_t*)(p0 + d) = pkh2(acc[mf][nf][0], acc[mf][nf][1]);
            *(uint32_t*)(p1 + d) = pkh2(acc[mf][nf][2], acc[mf][nf][3]);
        }
    }
}

// ---------------------------------------------------------------------------
// Kernel 3: output GEMM: d_out = g_ah @ Wo + bo. grid (4, 32) x 256.
// ---------------------------------------------------------------------------
__global__ __launch_bounds__(256, 2) void gemm_out_mma(
    const float* __restrict__ bo, float* __restrict__ Out)
{
    extern __shared__ __half dsm[];
    __half* As = dsm;
    __half* Bs = dsm + 4 * 128 * GSH;
    const __half* Bt = g_wh + (size_t)3 * DD * NINNER;
    int row0 = blockIdx.y * 128, col0 = blockIdx.x * 128;

    float acc[2][8][4];
    #pragma unroll
    for (int i = 0; i < 2; i++)
        #pragma unroll
        for (int j = 0; j < 8; j++)
            #pragma unroll
            for (int r = 0; r < 4; r++) acc[i][j][r] = 0.f;

    mma_mainloop_h(g_ah, Bt, row0, col0, As, Bs, acc);

    int tid = threadIdx.x, wid = tid >> 5, lane = tid & 31;
    int g = lane >> 2, tig = lane & 3;
    int wm = wid & 3, wn = wid >> 2;
    #pragma unroll
    for (int mf = 0; mf < 2; mf++) {
        int r0 = row0 + wm * 32 + mf * 16 + g;
        int r1 = r0 + 8;
        #pragma unroll
        for (int nf = 0; nf < 8; nf++) {
            int col = col0 + wn * 64 + nf * 8 + 2 * tig;
            float2 bias = *(const float2*)(bo + col);
            float2 o0, o1;
            o0.x = acc[mf][nf][0] + bias.x;
            o0.y = acc[mf][nf][1] + bias.y;
            o1.x = acc[mf][nf][2] + bias.x;
            o1.y = acc[mf][nf][3] + bias.y;
            *(float2*)(Out + (size_t)r0 * DD + col) = o0;
            *(float2*)(Out + (size_t)r1 * DD + col) = o1;
        }
    }
}

// ---------------------------------------------------------------------------
// Kernel 2a: split-KV causal attention, 64-key chunks (two 32-key halves),
// 4-stage ring, ONE wait+barrier per TWO chunks. Fixed-zero softmax
// reference, fp16x2 exp, l via ones-MMA. qt<4 writes g_ah directly.
// grid (40, 16) x 256. Dynamic smem.
// ---------------------------------------------------------------------------
#define KSH 72
#define VSH 72
#define KST (64 * KSH * 2)            // per-stage bytes per matrix (9216)
#define ASMEM (4 * KST * 2)           // 73728 bytes

__global__ __launch_bounds__(256, 2) void attn_mma() {
    extern __shared__ __half dsm[];
    __half* Kb = dsm;
    __half* Vb = dsm + 4 * 64 * KSH;

    int u = blockIdx.x;
    int qt = c_qt[u], seg = c_sg[u];
    int bh = blockIdx.y, h = bh & (HH-1);
    int tid = threadIdx.x, wid = tid >> 5, lane = tid & 31;
    int g = lane >> 2, tig = lane & 3;
    int sub = lane >> 3, lr = lane & 7;
    int q0 = qt * 128 + wid * 16;

    int kstart = seg * 512;
    int kend = min((seg + 1) * 512, (qt + 1) * 128);
    int nch = (kend - kstart) >> 6;       // always even (length multiple of 128)

    const __half* qp = g_qh + (size_t)bh * TT * DH;
    const __half* kp = g_kh + (size_t)bh * TT * DH;
    const __half* vp = g_vh + (size_t)bh * TT * DH;

    float bias[MAXLAG+1];
    {
        float c5 = g_lagp[h*(MAXLAG+1) + MAXLAG];
        #pragma unroll
        for (int i = 0; i <= MAXLAG; i++)
            bias[i] = (g_lagp[h*(MAXLAG+1)+i] - c5) * LOG2E;
    }

    const __half2 qs2 = __float2half2_rn(0.125f * LOG2E);
    uint32_t qa[4][4];
    #pragma unroll
    for (int kf = 0; kf < 4; kf++) {
        __half2 v0 = *(const __half2*)&qp[(size_t)(q0 + g    ) * DH + kf*16 + 2*tig];
        __half2 v1 = *(const __half2*)&qp[(size_t)(q0 + 8 + g) * DH + kf*16 + 2*tig];
        __half2 v2 = *(const __half2*)&qp[(size_t)(q0 + g    ) * DH + kf*16 + 8 + 2*tig];
        __half2 v3 = *(const __half2*)&qp[(size_t)(q0 + 8 + g) * DH + kf*16 + 8 + 2*tig];
        v0 = __hmul2(v0, qs2); v1 = __hmul2(v1, qs2);
        v2 = __hmul2(v2, qs2); v3 = __hmul2(v3, qs2);
        qa[kf][0] = *(uint32_t*)&v0; qa[kf][1] = *(uint32_t*)&v1;
        qa[kf][2] = *(uint32_t*)&v2; qa[kf][3] = *(uint32_t*)&v3;
    }

    float O[8][4];
    #pragma unroll
    for (int i = 0; i < 8; i++)
        #pragma unroll
        for (int r = 0; r < 4; r++) O[i][r] = 0.f;
    float lacc[4] = {0.f, 0.f, 0.f, 0.f};
    int qiA = q0 + g, qiB = q0 + 8 + g;
    const uint32_t ONES = 0x3C003C00u;

    int r8 = tid >> 3, c8 = tid & 7;
    uint32_t kd0 = smem_u32(&Kb[r8 * KSH + c8 * 8]);
    uint32_t vd0 = smem_u32(&Vb[r8 * VSH + c8 * 8]);
    uint32_t sK0 = smem_u32(Kb) + (((sub>>1)*8 + lr) * KSH + (sub&1)*8) * 2;
    uint32_t sV0 = smem_u32(Vb) + (((sub&1)*8 + lr) * VSH + (sub>>1)*8) * 2;

    const char* kg = (const char*)(kp + (size_t)(kstart + r8) * DH + c8 * 8);
    const char* vg = (const char*)(vp + (size_t)(kstart + r8) * DH + c8 * 8);
    const long CHB = (long)64 * DH * 2;
    const long HS  = (long)32 * DH * 2;
    const uint32_t HSs = 32 * KSH * 2;

    #pragma unroll
    for (int c0 = 0; c0 < 2; c0++) {
        long off = (long)c0 * CHB;
        uint32_t sb = c0 * KST;
        CP_ASYNC16(kd0 + sb, kg + off);       CP_ASYNC16(kd0 + sb + HSs, kg + off + HS);
        CP_ASYNC16(vd0 + sb, vg + off);       CP_ASYNC16(vd0 + sb + HSs, vg + off + HS);
        CP_COMMIT();
    }

    for (int c = 0; c < nch; c += 2) {
        CP_WAIT0();
        __syncthreads();
        #pragma unroll
        for (int f = 2; f < 4; f++) {
            if (c + f < nch) {
                uint32_t sb = ((c + f) & 3) * KST;
                long off = (long)(c + f) * CHB;
                CP_ASYNC16(kd0 + sb, kg + off);       CP_ASYNC16(kd0 + sb + HSs, kg + off + HS);
                CP_ASYNC16(vd0 + sb, vg + off);       CP_ASYNC16(vd0 + sb + HSs, vg + off + HS);
                CP_COMMIT();
            }
        }
        #pragma unroll
        for (int d = 0; d < 2; d++) {
            int cc = c + d;
            int j0 = kstart + cc * 64;
            if (j0 > q0 + 15) continue;
            uint32_t st = (uint32_t)(cc & 3) * KST;
            uint32_t sK = sK0 + st;
            uint32_t sV = sV0 + st;
            // S for both halves
            float s1[4][4], s2[4][4];
            #pragma unroll
            for (int nf = 0; nf < 4; nf++)
                #pragma unroll
                for (int r = 0; r < 4; r++) { s1[nf][r] = 0.f; s2[nf][r] = 0.f; }
            #pragma unroll
            for (int hb = 0; hb < 2; hb++) {
                float (*s)[4] = hb ? s2 : s1;
                #pragma unroll
                for (int kf = 0; kf < 4; kf++) {
                    #pragma unroll
                    for (int p = 0; p < 2; p++) {
                        uint32_t b0, b1, b2, b3;
                        LDSM4(b0, b1, b2, b3,
                              sK + (2*hb + p) * (16 * KSH * 2) + kf * 32);
                        mma16(s[2*p],   qa[kf], b0, b1);
                        mma16(s[2*p+1], qa[kf], b2, b3);
                    }
                }
            }
            // per-half: bias/mask -> exp -> PV(+l)
            #pragma unroll
            for (int hb = 0; hb < 2; hb++) {
                float (*s)[4] = hb ? s2 : s1;
                int jb = j0 + hb * 32;
                if (jb + 36 > q0) {
                    #pragma unroll
                    for (int nf = 0; nf < 4; nf++) {
                        int jc = jb + nf * 8 + 2 * tig;
                        #pragma unroll
                        for (int uu = 0; uu < 2; uu++) {
                            int jj = jc + uu;
                            int lagA = qiA - jj; lagA = lagA < 0 ? 0 : (lagA > MAXLAG ? MAXLAG : lagA);
                            int lagB = qiB - jj; lagB = lagB < 0 ? 0 : (lagB > MAXLAG ? MAXLAG : lagB);
                            s[nf][uu]   = (jj <= qiA) ? (s[nf][uu]   + bias[lagA]) : -1e30f;
                            s[nf][2+uu] = (jj <= qiB) ? (s[nf][2+uu] + bias[lagB]) : -1e30f;
                        }
                    }
                }
                uint32_t pfrag[2][4];
                #pragma unroll
                for (int nf = 0; nf < 4; nf++) {
                    uint32_t e0 = pkh2(s[nf][0], s[nf][1]);
                    uint32_t e1 = pkh2(s[nf][2], s[nf][3]);
                    EX2H2(e0); EX2H2(e1);
                    pfrag[nf >> 1][(nf & 1) * 2]     = e0;
                    pfrag[nf >> 1][(nf & 1) * 2 + 1] = e1;
                }
                #pragma unroll
                for (int kk = 0; kk < 2; kk++) {
                    mma16(lacc, pfrag[kk], ONES, ONES);
                    #pragma unroll
                    for (int p = 0; p < 4; p++) {
                        uint32_t b0, b1, b2, b3;
                        LDSM4T(b0, b1, b2, b3,
                               sV + (2*hb + kk) * (16 * VSH * 2) + p * 32);
                        mma16(O[2*p],   pfrag[kk], b0, b1);
                        mma16(O[2*p+1], pfrag[kk], b2, b3);
                    }
                }
            }
        }
    }

    float lA = lacc[0], lB = lacc[2];
    int rA = wid * 16 + g, rB = rA + 8;

    if (qt < 4) {
        float invA = 1.f / lA, invB = 1.f / lB;
        int b_ = bh >> 3;
        int qA = qt * 128 + rA, qB = qt * 128 + rB;
        __half* pA = g_ah + ((size_t)(b_ * TT + qA)) * NINNER + h * DH;
        __half* pB = g_ah + ((size_t)(b_ * TT + qB)) * NINNER + h * DH;
        #pragma unroll
        for (int nf = 0; nf < 8; nf++) {
            int d = nf * 8 + 2 * tig;
            *(uint32_t*)(pA + d) = pkh2(O[nf][0] * invA, O[nf][1] * invA);
            *(uint32_t*)(pB + d) = pkh2(O[nf][2] * invB, O[nf][3] * invB);
        }
    } else {
        int base = (bh * NQT + qt) * MAXSEG + seg;
        float* pO = g_pO + (size_t)base * 128 * 64;
        #pragma unroll
        for (int nf = 0; nf < 8; nf++) {
            int d = nf * 8 + 2 * tig;
            *(float2*)(pO + rA * 64 + d) = make_float2(O[nf][0], O[nf][1]);
            *(float2*)(pO + rB * 64 + d) = make_float2(O[nf][2], O[nf][3]);
        }
        if (tig == 0) {
            g_pl[base * 128 + rA] = lA;
            g_pl[base * 128 + rB] = lB;
        }
    }
}

// ---------------------------------------------------------------------------
// Kernel 2b: combine partials -> g_ah (half), qt >= 4 only. grid (12,16)x256.
// ---------------------------------------------------------------------------
__global__ __launch_bounds__(256) void attn_combine() {
    int qt = blockIdx.x + 4, bh = blockIdx.y;
    int h = bh & (HH-1), b_ = bh >> 3;
    int nseg = (qt >> 2) + 1;
    int base0 = (bh * NQT + qt) * MAXSEG;
    int tid = threadIdx.x;

    #pragma unroll
    for (int it = 0; it < 8; it++) {
        int p = tid + it * 256;
        int r = p >> 4, d4 = p & 15;
        float L = 0.f;
        for (int s = 0; s < nseg; s++)
            L += g_pl[(base0 + s) * 128 + r];
        float inv = 1.f / L;
        float4 a = make_float4(0.f, 0.f, 0.f, 0.f);
        for (int s = 0; s < nseg; s++) {
            const float4 v = *(const float4*)(g_pO +
                ((size_t)(base0 + s) * 128 + r) * 64 + d4 * 4);
            a.x += v.x; a.y += v.y; a.z += v.z; a.w += v.w;
        }
        int qi = qt * 128 + r;
        size_t ob = ((size_t)(b_ * TT + qi)) * NINNER + h * DH + d4 * 4;
        *(uint2*)(g_ah + ob) = make_uint2(pkh2(a.x * inv, a.y * inv),
                                          pkh2(a.z * inv, a.w * inv));
    }
}

// ---------------------------------------------------------------------------
extern "C" void kernel_launch(void* const* d_in, const int* in_sizes, int n_in,
                              void* d_out, int out_size) {
    const float* x  = (const float*)d_in[0];
    const float* Wq = (const float*)d_in[1];
    const float* Wk = (const float*)d_in[2];
    const float* Wv = (const float*)d_in[3];
    const float* Wo = (const float*)d_in[4];
    const float* bo = (const float*)d_in[5];
    const float* lw = (const float*)d_in[6];
    float* out = (float*)d_out;

    cudaFuncSetAttribute(gemm_qkv_mma, cudaFuncAttributeMaxDynamicSharedMemorySize, GSMEM);
    cudaFuncSetAttribute(gemm_out_mma, cudaFuncAttributeMaxDynamicSharedMemorySize, GSMEM);
    cudaFuncSetAttribute(attn_mma,     cudaFuncAttributeMaxDynamicSharedMemorySize, ASMEM);

    cvt_x_kernel<<<BT*DD/2048, 256>>>(x, lw);
    transpose_w_kernel<<<dim3(16, 16, 4), 256>>>(Wq, Wk, Wv, Wo);
    gemm_qkv_mma<<<dim3(NINNER/128, BT/128, 3), 256, GSMEM>>>();
    attn_mma<<<dim3(40, NBH), 256, ASMEM>>>();
    attn_combine<<<dim3(12, NBH), 256>>>();
    gemm_out_mma<<<dim3(DD/128, BT/128), 256, GSMEM>>>(bo, out);
}

// round 16
// speedup vs baseline: 1.0762x; 1.0762x over previous
#include <cuda_runtime.h>
#include <cuda_fp16.h>
#include <cstdint>

#define BB 2
#define TT 2048
#define DD 512
#define HH 8
#define DH 64
#define NINNER 512
#define MAXLAG 5
#define BT (BB*TT)
#define NBH (BB*HH)
#define NQT 16
#define MAXSEG 4
#define LOG2E 1.4426950408889634f

// Scratch (device globals; no allocation allowed)
__device__ __half g_qh[BB*HH*TT*DH];
__device__ __half g_kh[BB*HH*TT*DH];
__device__ __half g_vh[BB*HH*TT*DH];
__device__ __half g_ah[BT*NINNER];
__device__ __half g_xh[BT*DD];
__device__ __half g_wh[4*DD*NINNER];   // W^T (half): WT[n][k] = W[k][n]
__device__ float g_lagp[HH*(MAXLAG+1)];
// split-KV partials
__device__ float g_pO[NBH*NQT*MAXSEG*128*64];
__device__ float g_pl[NBH*NQT*MAXSEG*128];

// work-unit table, LPT order
__device__ const uint8_t c_qt[40] = {
    3,4,5,6,7,7,8,8,9,9,10,10,11,11,11,12,12,12,13,13,13,14,14,14,15,15,15,15,
    2,6,10,14, 1,5,9,13, 0,4,8,12};
__device__ const uint8_t c_sg[40] = {
    0,0,0,0,0,1,0,1,0,1,0,1,0,1,2,0,1,2,0,1,2,0,1,2,0,1,2,3,
    0,1,2,3, 0,1,2,3, 0,1,2,3};

// ---------------------------------------------------------------------------
static __device__ __forceinline__ uint32_t pkh2(float a, float b) {
    __half2 h = __floats2half2_rn(a, b);
    return *(uint32_t*)&h;
}
static __device__ __forceinline__ void mma16(float* d, const uint32_t* a,
                                             uint32_t b0, uint32_t b1) {
    asm volatile(
        "mma.sync.aligned.m16n8k16.row.col.f32.f16.f16.f32 "
        "{%0,%1,%2,%3},{%4,%5,%6,%7},{%8,%9},{%0,%1,%2,%3};"
        : "+f"(d[0]), "+f"(d[1]), "+f"(d[2]), "+f"(d[3])
        : "r"(a[0]), "r"(a[1]), "r"(a[2]), "r"(a[3]), "r"(b0), "r"(b1));
}
#define EX2H2(v) asm("ex2.approx.f16x2 %0, %0;" : "+r"(v))
#define LDSM4(r0,r1,r2,r3, addr) \
    asm volatile("ldmatrix.sync.aligned.m8n8.x4.shared.b16 {%0,%1,%2,%3}, [%4];" \
        : "=r"(r0),"=r"(r1),"=r"(r2),"=r"(r3) : "r"(addr))
#define LDSM4T(r0,r1,r2,r3, addr) \
    asm volatile("ldmatrix.sync.aligned.m8n8.x4.trans.shared.b16 {%0,%1,%2,%3}, [%4];" \
        : "=r"(r0),"=r"(r1),"=r"(r2),"=r"(r3) : "r"(addr))
static __device__ __forceinline__ uint32_t smem_u32(const void* p) {
    uint32_t a;
    asm("{ .reg .u64 t; cvta.to.shared.u64 t, %1; cvt.u32.u64 %0, t; }" : "=r"(a) : "l"(p));
    return a;
}
#define CP_ASYNC16(dst, src) \
    asm volatile("cp.async.cg.shared.global [%0], [%1], 16;" :: "r"(dst), "l"(src))
#define CP_COMMIT() asm volatile("cp.async.commit_group;" ::: "memory")
#define CP_WAIT0()  asm volatile("cp.async.wait_group 0;" ::: "memory")
#define CP_WAIT1()  asm volatile("cp.async.wait_group 1;" ::: "memory")

// ---------------------------------------------------------------------------
// Kernel C: x (fp32) -> g_xh (half). Block 0 also computes lag softmax.
// ---------------------------------------------------------------------------
__global__ __launch_bounds__(256) void cvt_x_kernel(
    const float* __restrict__ x, const float* __restrict__ lw)
{
    int i = blockIdx.x * 256 + threadIdx.x;
    float4 v0 = ((const float4*)x)[2*i];
    float4 v1 = ((const float4*)x)[2*i + 1];
    uint4 o = make_uint4(pkh2(v0.x, v0.y), pkh2(v0.z, v0.w),
                         pkh2(v1.x, v1.y), pkh2(v1.z, v1.w));
    ((uint4*)g_xh)[i] = o;

    if (blockIdx.x == 0 && threadIdx.x < HH) {
        int h = threadIdx.x;
        float vals[MAXLAG+1];
        float m = -1e30f;
        #pragma unroll
        for (int k = 0; k <= MAXLAG; k++) { vals[k] = lw[h*(MAXLAG+1)+k]; m = fmaxf(m, vals[k]); }
        float s = 0.f;
        #pragma unroll
        for (int k = 0; k <= MAXLAG; k++) { vals[k] = __expf(vals[k]-m); s += vals[k]; }
        #pragma unroll
        for (int k = 0; k <= MAXLAG; k++) g_lagp[h*(MAXLAG+1)+k] = vals[k]/s;
    }
}

// ---------------------------------------------------------------------------
// Kernel T: transpose 4 weight matrices -> g_wh (half W^T)
// ---------------------------------------------------------------------------
__global__ __launch_bounds__(256) void transpose_w_kernel(
    const float* __restrict__ Wq, const float* __restrict__ Wk,
    const float* __restrict__ Wv, const float* __restrict__ Wo)
{
    __shared__ float tile[32][33];
    const float* W = (blockIdx.z == 0) ? Wq : (blockIdx.z == 1) ? Wk
                    : (blockIdx.z == 2) ? Wv : Wo;
    __half* WT = g_wh + (size_t)blockIdx.z * DD * NINNER;
    int x0 = blockIdx.x * 32, y0 = blockIdx.y * 32;
    int tx = threadIdx.x & 31, ty = threadIdx.x >> 5;
    #pragma unroll
    for (int i = 0; i < 4; i++)
        tile[ty + i*8][tx] = W[(size_t)(y0 + ty + i*8) * NINNER + x0 + tx];
    __syncthreads();
    #pragma unroll
    for (int i = 0; i < 4; i++)
        WT[(size_t)(x0 + ty + i*8) * DD + y0 + tx] = __float2half(tile[tx][ty + i*8]);
}

// ---------------------------------------------------------------------------
// fp16 GEMM mainloop (R13 config): 128x128 tile, K=512, static 3-stage
// cp.async, wait_group 1, per-chunk sync, B-fragment pipeline.
// ---------------------------------------------------------------------------
#define GSH 40

static __device__ __forceinline__ void mma_mainloop_h(
    const __half* __restrict__ A, const __half* __restrict__ Bt,
    int row0, int col0, __half* As, __half* Bs, float acc[2][8][4])
{
    int tid = threadIdx.x, wid = tid >> 5, lane = tid & 31;
    int sub = lane >> 3, lr = lane & 7;
    int wm = wid & 3, wn = wid >> 2;
    int m0 = wm * 32, n0 = wn * 64;

    int fr = tid >> 2, fc = tid & 3;
    const char* pa = (const char*)(A  + (size_t)(row0 + fr) * DD + fc * 8);
    const char* pb = (const char*)(Bt + (size_t)(col0 + fr) * DD + fc * 8);
    const long RS = (long)64 * DD * 2;

    uint32_t ad[3][2], bd[3][2], sAb[3], sBb[3];
    #pragma unroll
    for (int st = 0; st < 3; st++) {
        sAb[st] = smem_u32(As + st * 128 * GSH);
        sBb[st] = smem_u32(Bs + st * 128 * GSH);
        #pragma unroll
        for (int i = 0; i < 2; i++) {
            ad[st][i] = smem_u32(&As[st*128*GSH + (fr + i*64) * GSH + fc * 8]);
            bd[st][i] = smem_u32(&Bs[st*128*GSH + (fr + i*64) * GSH + fc * 8]);
        }
    }
    uint32_t aoff = ((m0 + (sub&1)*8 + lr) * GSH + (sub>>1)*8) * 2;
    uint32_t boff = ((n0 + (sub>>1)*8 + lr) * GSH + (sub&1)*8) * 2;

    #pragma unroll
    for (int c0 = 0; c0 < 2; c0++) {
        long off = (long)c0 * 64;
        #pragma unroll
        for (int i = 0; i < 2; i++) {
            CP_ASYNC16(ad[c0][i], pa + i * RS + off);
            CP_ASYNC16(bd[c0][i], pb + i * RS + off);
        }
        CP_COMMIT();
    }

    for (int c = 0; c < 16; c++) {
        int st = c % 3;
        CP_WAIT1();
        __syncthreads();
        if (c + 2 < 16) {
            int s2 = (c + 2) % 3;
            long off = (long)(c + 2) * 64;
            #pragma unroll
            for (int i = 0; i < 2; i++) {
                CP_ASYNC16(ad[s2][i], pa + i * RS + off);
                CP_ASYNC16(bd[s2][i], pb + i * RS + off);
            }
        }
        CP_COMMIT();

        uint32_t sA = sAb[st] + aoff, sB = sBb[st] + boff;
        uint32_t a[2][2][4];
        #pragma unroll
        for (int kk = 0; kk < 2; kk++)
            #pragma unroll
            for (int mf = 0; mf < 2; mf++)
                LDSM4(a[kk][mf][0], a[kk][mf][1], a[kk][mf][2], a[kk][mf][3],
                      sA + mf * (16 * GSH * 2) + kk * 32);
        uint32_t bB[2][4];
        LDSM4(bB[0][0], bB[0][1], bB[0][2], bB[0][3], sB);
        #pragma unroll
        for (int it = 0; it < 8; it++) {
            int kk = it >> 2, p = it & 3;
            if (it + 1 < 8) {
                int nkk = (it + 1) >> 2, np = (it + 1) & 3;
                LDSM4(bB[(it+1)&1][0], bB[(it+1)&1][1], bB[(it+1)&1][2], bB[(it+1)&1][3],
                      sB + np * (16 * GSH * 2) + nkk * 32);
            }
            const uint32_t* b = bB[it & 1];
            mma16(acc[0][2*p],   a[kk][0], b[0], b[1]);
            mma16(acc[0][2*p+1], a[kk][0], b[2], b[3]);
            mma16(acc[1][2*p],   a[kk][1], b[0], b[1]);
            mma16(acc[1][2*p+1], a[kk][1], b[2], b[3]);
        }
    }
}

// ---------------------------------------------------------------------------
// Kernel 1: QKV GEMM. grid (4, 32, 3) x 256. Writes half [b,h,t,d].
// ---------------------------------------------------------------------------
__global__ __launch_bounds__(256, 2) void gemm_qkv_mma() {
    __shared__ __half As[3 * 128 * GSH];
    __shared__ __half Bs[3 * 128 * GSH];
    int z = blockIdx.z;
    const __half* Bt = g_wh + (size_t)z * DD * NINNER;
    __half* out = (z == 0) ? g_qh : (z == 1) ? g_kh : g_vh;
    int row0 = blockIdx.y * 128, col0 = blockIdx.x * 128;

    float acc[2][8][4];
    #pragma unroll
    for (int i = 0; i < 2; i++)
        #pragma unroll
        for (int j = 0; j < 8; j++)
            #pragma unroll
            for (int r = 0; r < 4; r++) acc[i][j][r] = 0.f;

    mma_mainloop_h(g_xh, Bt, row0, col0, As, Bs, acc);

    int tid = threadIdx.x, wid = tid >> 5, lane = tid & 31;
    int g = lane >> 2, tig = lane & 3;
    int wm = wid & 3, wn = wid >> 2;
    int h = (col0 >> 6) + wn;
    #pragma unroll
    for (int mf = 0; mf < 2; mf++) {
        int r0 = row0 + wm * 32 + mf * 16 + g;
        int r1 = r0 + 8;
        int b0_ = r0 >> 11, t0 = r0 & (TT-1);
        int b1_ = r1 >> 11, t1 = r1 & (TT-1);
        __half* p0 = out + ((size_t)(b0_*HH + h)*TT + t0)*DH;
        __half* p1 = out + ((size_t)(b1_*HH + h)*TT + t1)*DH;
        #pragma unroll
        for (int nf = 0; nf < 8; nf++) {
            int d = nf * 8 + 2 * tig;
            *(uint32_t*)(p0 + d) = pkh2(acc[mf][nf][0], acc[mf][nf][1]);
            *(uint32_t*)(p1 + d) = pkh2(acc[mf][nf][2], acc[mf][nf][3]);
        }
    }
}

// ---------------------------------------------------------------------------
// Kernel 3: output GEMM: d_out = g_ah @ Wo + bo. grid (4, 32) x 256.
// ---------------------------------------------------------------------------
__global__ __launch_bounds__(256, 2) void gemm_out_mma(
    const float* __restrict__ bo, float* __restrict__ Out)
{
    __shared__ __half As[3 * 128 * GSH];
    __shared__ __half Bs[3 * 128 * GSH];
    const __half* Bt = g_wh + (size_t)3 * DD * NINNER;
    int row0 = blockIdx.y * 128, col0 = blockIdx.x * 128;

    float acc[2][8][4];
    #pragma unroll
    for (int i = 0; i < 2; i++)
        #pragma unroll
        for (int j = 0; j < 8; j++)
            #pragma unroll
            for (int r = 0; r < 4; r++) acc[i][j][r] = 0.f;

    mma_mainloop_h(g_ah, Bt, row0, col0, As, Bs, acc);

    int tid = threadIdx.x, wid = tid >> 5, lane = tid & 31;
    int g = lane >> 2, tig = lane & 3;
    int wm = wid & 3, wn = wid >> 2;
    #pragma unroll
    for (int mf = 0; mf < 2; mf++) {
        int r0 = row0 + wm * 32 + mf * 16 + g;
        int r1 = r0 + 8;
        #pragma unroll
        for (int nf = 0; nf < 8; nf++) {
            int col = col0 + wn * 64 + nf * 8 + 2 * tig;
            float2 bias = *(const float2*)(bo + col);
            float2 o0, o1;
            o0.x = acc[mf][nf][0] + bias.x;
            o0.y = acc[mf][nf][1] + bias.y;
            o1.x = acc[mf][nf][2] + bias.x;
            o1.y = acc[mf][nf][3] + bias.y;
            *(float2*)(Out + (size_t)r0 * DD + col) = o0;
            *(float2*)(Out + (size_t)r1 * DD + col) = o1;
        }
    }
}

// ---------------------------------------------------------------------------
// Kernel 2a: split-KV causal attention (R15 config): 64-key chunks (two
// 32-key halves), 4-stage ring, ONE wait+barrier per TWO chunks.
// Fixed-zero softmax reference, fp16x2 exp, l via ones-MMA. qt<4 direct.
// grid (40, 16) x 256. Dynamic smem.
// ---------------------------------------------------------------------------
#define KSH 72
#define VSH 72
#define KST (64 * KSH * 2)            // per-stage bytes per matrix (9216)
#define ASMEM (4 * KST * 2)           // 73728 bytes

__global__ __launch_bounds__(256, 2) void attn_mma() {
    extern __shared__ __half dsm[];
    __half* Kb = dsm;
    __half* Vb = dsm + 4 * 64 * KSH;

    int u = blockIdx.x;
    int qt = c_qt[u], seg = c_sg[u];
    int bh = blockIdx.y, h = bh & (HH-1);
    int tid = threadIdx.x, wid = tid >> 5, lane = tid & 31;
    int g = lane >> 2, tig = lane & 3;
    int sub = lane >> 3, lr = lane & 7;
    int q0 = qt * 128 + wid * 16;

    int kstart = seg * 512;
    int kend = min((seg + 1) * 512, (qt + 1) * 128);
    int nch = (kend - kstart) >> 6;

    const __half* qp = g_qh + (size_t)bh * TT * DH;
    const __half* kp = g_kh + (size_t)bh * TT * DH;
    const __half* vp = g_vh + (size_t)bh * TT * DH;

    float bias[MAXLAG+1];
    {
        float c5 = g_lagp[h*(MAXLAG+1) + MAXLAG];
        #pragma unroll
        for (int i = 0; i <= MAXLAG; i++)
            bias[i] = (g_lagp[h*(MAXLAG+1)+i] - c5) * LOG2E;
    }

    const __half2 qs2 = __float2half2_rn(0.125f * LOG2E);
    uint32_t qa[4][4];
    #pragma unroll
    for (int kf = 0; kf < 4; kf++) {
        __half2 v0 = *(const __half2*)&qp[(size_t)(q0 + g    ) * DH + kf*16 + 2*tig];
        __half2 v1 = *(const __half2*)&qp[(size_t)(q0 + 8 + g) * DH + kf*16 + 2*tig];
        __half2 v2 = *(const __half2*)&qp[(size_t)(q0 + g    ) * DH + kf*16 + 8 + 2*tig];
        __half2 v3 = *(const __half2*)&qp[(size_t)(q0 + 8 + g) * DH + kf*16 + 8 + 2*tig];
        v0 = __hmul2(v0, qs2); v1 = __hmul2(v1, qs2);
        v2 = __hmul2(v2, qs2); v3 = __hmul2(v3, qs2);
        qa[kf][0] = *(uint32_t*)&v0; qa[kf][1] = *(uint32_t*)&v1;
        qa[kf][2] = *(uint32_t*)&v2; qa[kf][3] = *(uint32_t*)&v3;
    }

    float O[8][4];
    #pragma unroll
    for (int i = 0; i < 8; i++)
        #pragma unroll
        for (int r = 0; r < 4; r++) O[i][r] = 0.f;
    float lacc[4] = {0.f, 0.f, 0.f, 0.f};
    int qiA = q0 + g, qiB = q0 + 8 + g;
    const uint32_t ONES = 0x3C003C00u;

    int r8 = tid >> 3, c8 = tid & 7;
    uint32_t kd0 = smem_u32(&Kb[r8 * KSH + c8 * 8]);
    uint32_t vd0 = smem_u32(&Vb[r8 * VSH + c8 * 8]);
    uint32_t sK0 = smem_u32(Kb) + (((sub>>1)*8 + lr) * KSH + (sub&1)*8) * 2;
    uint32_t sV0 = smem_u32(Vb) + (((sub&1)*8 + lr) * VSH + (sub>>1)*8) * 2;

    const char* kg = (const char*)(kp + (size_t)(kstart + r8) * DH + c8 * 8);
    const char* vg = (const char*)(vp + (size_t)(kstart + r8) * DH + c8 * 8);
    const long CHB = (long)64 * DH * 2;
    const long HS  = (long)32 * DH * 2;
    const uint32_t HSs = 32 * KSH * 2;

    #pragma unroll
    for (int c0 = 0; c0 < 2; c0++) {
        long off = (long)c0 * CHB;
        uint32_t sb = c0 * KST;
        CP_ASYNC16(kd0 + sb, kg + off);       CP_ASYNC16(kd0 + sb + HSs, kg + off + HS);
        CP_ASYNC16(vd0 + sb, vg + off);       CP_ASYNC16(vd0 + sb + HSs, vg + off + HS);
        CP_COMMIT();
    }

    for (int c = 0; c < nch; c += 2) {
        CP_WAIT0();
        __syncthreads();
        #pragma unroll
        for (int f = 2; f < 4; f++) {
            if (c + f < nch) {
                uint32_t sb = ((c + f) & 3) * KST;
                long off = (long)(c + f) * CHB;
                CP_ASYNC16(kd0 + sb, kg + off);       CP_ASYNC16(kd0 + sb + HSs, kg + off + HS);
                CP_ASYNC16(vd0 + sb, vg + off);       CP_ASYNC16(vd0 + sb + HSs, vg + off + HS);
                CP_COMMIT();
            }
        }
        #pragma unroll
        for (int d = 0; d < 2; d++) {
            int cc = c + d;
            int j0 = kstart + cc * 64;
            if (j0 > q0 + 15) continue;
            uint32_t st = (uint32_t)(cc & 3) * KST;
            uint32_t sK = sK0 + st;
            uint32_t sV = sV0 + st;
            float s1[4][4], s2[4][4];
            #pragma unroll
            for (int nf = 0; nf < 4; nf++)
                #pragma unroll
                for (int r = 0; r < 4; r++) { s1[nf][r] = 0.f; s2[nf][r] = 0.f; }
            #pragma unroll
            for (int hb = 0; hb < 2; hb++) {
                float (*s)[4] = hb ? s2 : s1;
                #pragma unroll
                for (int kf = 0; kf < 4; kf++) {
                    #pragma unroll
                    for (int p = 0; p < 2; p++) {
                        uint32_t b0, b1, b2, b3;
                        LDSM4(b0, b1, b2, b3,
                              sK + (2*hb + p) * (16 * KSH * 2) + kf * 32);
                        mma16(s[2*p],   qa[kf], b0, b1);
                        mma16(s[2*p+1], qa[kf], b2, b3);
                    }
                }
            }
            #pragma unroll
            for (int hb = 0; hb < 2; hb++) {
                float (*s)[4] = hb ? s2 : s1;
                int jb = j0 + hb * 32;
                if (jb + 36 > q0) {
                    #pragma unroll
                    for (int nf = 0; nf < 4; nf++) {
                        int jc = jb + nf * 8 + 2 * tig;
                        #pragma unroll
                        for (int uu = 0; uu < 2; uu++) {
                            int jj = jc + uu;
                            int lagA = qiA - jj; lagA = lagA < 0 ? 0 : (lagA > MAXLAG ? MAXLAG : lagA);
                            int lagB = qiB - jj; lagB = lagB < 0 ? 0 : (lagB > MAXLAG ? MAXLAG : lagB);
                            s[nf][uu]   = (jj <= qiA) ? (s[nf][uu]   + bias[lagA]) : -1e30f;
                            s[nf][2+uu] = (jj <= qiB) ? (s[nf][2+uu] + bias[lagB]) : -1e30f;
                        }
                    }
                }
                uint32_t pfrag[2][4];
                #pragma unroll
                for (int nf = 0; nf < 4; nf++) {
                    uint32_t e0 = pkh2(s[nf][0], s[nf][1]);
                    uint32_t e1 = pkh2(s[nf][2], s[nf][3]);
                    EX2H2(e0); EX2H2(e1);
                    pfrag[nf >> 1][(nf & 1) * 2]     = e0;
                    pfrag[nf >> 1][(nf & 1) * 2 + 1] = e1;
                }
                #pragma unroll
                for (int kk = 0; kk < 2; kk++) {
                    mma16(lacc, pfrag[kk], ONES, ONES);
                    #pragma unroll
                    for (int p = 0; p < 4; p++) {
                        uint32_t b0, b1, b2, b3;
                        LDSM4T(b0, b1, b2, b3,
                               sV + (2*hb + kk) * (16 * VSH * 2) + p * 32);
                        mma16(O[2*p],   pfrag[kk], b0, b1);
                        mma16(O[2*p+1], pfrag[kk], b2, b3);
                    }
                }
            }
        }
    }

    float lA = lacc[0], lB = lacc[2];
    int rA = wid * 16 + g, rB = rA + 8;

    if (qt < 4) {
        float invA = 1.f / lA, invB = 1.f / lB;
        int b_ = bh >> 3;
        int qA = qt * 128 + rA, qB = qt * 128 + rB;
        __half* pA = g_ah + ((size_t)(b_ * TT + qA)) * NINNER + h * DH;
        __half* pB = g_ah + ((size_t)(b_ * TT + qB)) * NINNER + h * DH;
        #pragma unroll
        for (int nf = 0; nf < 8; nf++) {
            int d = nf * 8 + 2 * tig;
            *(uint32_t*)(pA + d) = pkh2(O[nf][0] * invA, O[nf][1] * invA);
            *(uint32_t*)(pB + d) = pkh2(O[nf][2] * invB, O[nf][3] * invB);
        }
    } else {
        int base = (bh * NQT + qt) * MAXSEG + seg;
        float* pO = g_pO + (size_t)base * 128 * 64;
        #pragma unroll
        for (int nf = 0; nf < 8; nf++) {
            int d = nf * 8 + 2 * tig;
            *(float2*)(pO + rA * 64 + d) = make_float2(O[nf][0], O[nf][1]);
            *(float2*)(pO + rB * 64 + d) = make_float2(O[nf][2], O[nf][3]);
        }
        if (tig == 0) {
            g_pl[base * 128 + rA] = lA;
            g_pl[base * 128 + rB] = lB;
        }
    }
}

// ---------------------------------------------------------------------------
// Kernel 2b: combine partials -> g_ah (half), qt >= 4 only. grid (12,16)x256.
// ---------------------------------------------------------------------------
__global__ __launch_bounds__(256) void attn_combine() {
    int qt = blockIdx.x + 4, bh = blockIdx.y;
    int h = bh & (HH-1), b_ = bh >> 3;
    int nseg = (qt >> 2) + 1;
    int base0 = (bh * NQT + qt) * MAXSEG;
    int tid = threadIdx.x;

    #pragma unroll
    for (int it = 0; it < 8; it++) {
        int p = tid + it * 256;
        int r = p >> 4, d4 = p & 15;
        float L = 0.f;
        for (int s = 0; s < nseg; s++)
            L += g_pl[(base0 + s) * 128 + r];
        float inv = 1.f / L;
        float4 a = make_float4(0.f, 0.f, 0.f, 0.f);
        for (int s = 0; s < nseg; s++) {
            const float4 v = *(const float4*)(g_pO +
                ((size_t)(base0 + s) * 128 + r) * 64 + d4 * 4);
            a.x += v.x; a.y += v.y; a.z += v.z; a.w += v.w;
        }
        int qi = qt * 128 + r;
        size_t ob = ((size_t)(b_ * TT + qi)) * NINNER + h * DH + d4 * 4;
        *(uint2*)(g_ah + ob) = make_uint2(pkh2(a.x * inv, a.y * inv),
                                          pkh2(a.z * inv, a.w * inv));
    }
}

// ---------------------------------------------------------------------------
extern "C" void kernel_launch(void* const* d_in, const int* in_sizes, int n_in,
                              void* d_out, int out_size) {
    const float* x  = (const float*)d_in[0];
    const float* Wq = (const float*)d_in[1];
    const float* Wk = (const float*)d_in[2];
    const float* Wv = (const float*)d_in[3];
    const float* Wo = (const float*)d_in[4];
    const float* bo = (const float*)d_in[5];
    const float* lw = (const float*)d_in[6];
    float* out = (float*)d_out;

    static bool attr_done = false;
    if (!attr_done) {
        cudaFuncSetAttribute(attn_mma, cudaFuncAttributeMaxDynamicSharedMemorySize, ASMEM);
        attr_done = true;
    }

    cvt_x_kernel<<<BT*DD/2048, 256>>>(x, lw);
    transpose_w_kernel<<<dim3(16, 16, 4), 256>>>(Wq, Wk, Wv, Wo);
    gemm_qkv_mma<<<dim3(NINNER/128, BT/128, 3), 256>>>();
    attn_mma<<<dim3(40, NBH), 256, ASMEM>>>();
    attn_combine<<<dim3(12, NBH), 256>>>();
    gemm_out_mma<<<dim3(DD/128, BT/128), 256>>>(bo, out);
}